// round 15
// baseline (speedup 1.0000x reference)
#include <cuda_runtime.h>
#include <cstdint>
#include <math.h>

// ---------------- constants -----------------
#define H 512
#define W 512
#define B 8
#define NPIX (B*H*W)          // 2097152

typedef unsigned long long ull;

// scratch (static device memory: allowed; no allocation)
__device__ float g_vxn[NPIX];
__device__ float g_vyn[NPIX];
__device__ float g_m0[NPIX];
__device__ float g_m1[NPIX];
__device__ int   g_list[NPIX];
__device__ int   g_count;
__device__ unsigned int g_keys[6];

// packed weights (float offsets), QUARTER-split with pads so the 4 lanes'
// bases are 16B apart mod 128 (conflict-free quad broadcasts):
//  W1Q[qt] @ qt*1028  (each 64c x 16 outputs = 1024 floats, pad 4)
//  W2Q[qt] @ 4112 + qt*516 (each 64c x 8 = 512 floats, pad 4)
//  WHID @6172 (256)  WRGB @6428 (96)  WVEL @6524 (64)
//  B1 @6588 (64)  B2 @6652 (32)  BRGB @6684 (3)  BVEL @6687 (2)  BHID @6692 (8)
#define WPACK_F 7168
__device__ float g_wpack[WPACK_F];

#define ACT_F        16384               // 64 ch x 256 px columns
#define SMEM_TOTAL_B ((ACT_F + WPACK_F) * 4)   // 94208 bytes

// act-tile swizzle: chunk (16B) index XORed with row>>3 so h-tile stores
// from 4 different row-groups land in distinct bank chunks.
#define ACHUNK(row, k)  ((row)*256 + ((((k) ^ ((row)>>3)) & 63) << 2))
#define AOFF(row, col)  (ACHUNK(row, (col)>>2) + ((col)&3))

// ---------------- packed f32x2 helpers -----------------
__device__ __forceinline__ ull pack2(float lo, float hi){
    ull r; asm("mov.b64 %0, {%1, %2};" : "=l"(r) : "f"(lo), "f"(hi)); return r;
}
__device__ __forceinline__ void unpack2(ull v, float& lo, float& hi){
    asm("mov.b64 {%0, %1}, %2;" : "=f"(lo), "=f"(hi) : "l"(v));
}
__device__ __forceinline__ ull ffma2(ull a, ull b, ull c){
    ull d; asm("fma.rn.f32x2 %0, %1, %2, %3;" : "=l"(d) : "l"(a), "l"(b), "l"(c)); return d;
}
__device__ __forceinline__ ull fmul2(ull a, ull b){
    ull d; asm("mul.rn.f32x2 %0, %1, %2;" : "=l"(d) : "l"(a), "l"(b)); return d;
}

// ---------------- threefry2x32 (bit-exact JAX, partitionable) -----------------
__device__ __forceinline__ uint32_t rotl32(uint32_t v, int r){ return (v<<r)|(v>>(32-r)); }

__device__ __forceinline__ void tf2x32(uint32_t k0, uint32_t k1, uint32_t x0, uint32_t x1,
                                       uint32_t& o0, uint32_t& o1){
    uint32_t k2 = k0 ^ k1 ^ 0x1BD11BDAu;
    x0 += k0; x1 += k1;
#define TFR(r) { x0 += x1; x1 = rotl32(x1,(r)); x1 ^= x0; }
    TFR(13) TFR(15) TFR(26) TFR(6)   x0 += k1; x1 += k2 + 1u;
    TFR(17) TFR(29) TFR(16) TFR(24)  x0 += k2; x1 += k0 + 2u;
    TFR(13) TFR(15) TFR(26) TFR(6)   x0 += k0; x1 += k1 + 3u;
    TFR(17) TFR(29) TFR(16) TFR(24)  x0 += k1; x1 += k2 + 4u;
    TFR(13) TFR(15) TFR(26) TFR(6)   x0 += k2; x1 += k0 + 5u;
#undef TFR
    o0 = x0; o1 = x1;
}

__device__ __forceinline__ uint32_t rng_bits(uint32_t k0, uint32_t k1, uint32_t i){
    uint32_t o0, o1;
    tf2x32(k0, k1, 0u, i, o0, o1);
    return o0 ^ o1;
}

__device__ __forceinline__ float bits_to_u01(uint32_t b){
    return __uint_as_float((b >> 9) | 0x3f800000u) - 1.0f;
}

// XLA ErfInv (f32, Giles polynomial)
__device__ __forceinline__ float erfinv32(float x){
    float w = -log1pf(-x*x);
    float p;
    if (w < 5.0f){
        w -= 2.5f;
        p = 2.81022636e-08f;
        p = fmaf(p, w, 3.43273939e-07f);
        p = fmaf(p, w, -3.5233877e-06f);
        p = fmaf(p, w, -4.39150654e-06f);
        p = fmaf(p, w, 0.00021858087f);
        p = fmaf(p, w, -0.00125372503f);
        p = fmaf(p, w, -0.00417768164f);
        p = fmaf(p, w, 0.246640727f);
        p = fmaf(p, w, 1.50140941f);
    } else {
        w = sqrtf(w) - 3.0f;
        p = -0.000200214257f;
        p = fmaf(p, w, 0.000100950558f);
        p = fmaf(p, w, 0.00134934322f);
        p = fmaf(p, w, -0.00367342844f);
        p = fmaf(p, w, 0.00573950773f);
        p = fmaf(p, w, -0.0076224613f);
        p = fmaf(p, w, 0.00943887047f);
        p = fmaf(p, w, 1.00167406f);
        p = fmaf(p, w, 2.83297682f);
    }
    return p * x;
}

// ---------------- key derivation (fold-like split, partitionable) ----------------
__global__ void key_setup(const int* __restrict__ seed){
    uint32_t K0 = 0u;
    uint32_t K1 = (uint32_t)(*seed);
    uint32_t nk0, nk1;
    tf2x32(K0, K1, 0u, 1u, nk0, nk1);
    uint32_t a0,a1,b0,b1;
    tf2x32(nk0, nk1, 0u, 0u, a0, a1);
    tf2x32(nk0, nk1, 0u, 1u, b0, b1);
    g_keys[0] = K0; g_keys[1] = K1;
    g_keys[2] = a0; g_keys[3] = a1;
    g_keys[4] = b0; g_keys[5] = b1;
    g_count = 0;
}

// ---------------- weight packing (quarter-split layout) ----------------
__global__ void prep_weights(const float* __restrict__ w1,  const float* __restrict__ b1,
                             const float* __restrict__ w2,  const float* __restrict__ b2,
                             const float* __restrict__ wrgb,const float* __restrict__ brgb,
                             const float* __restrict__ wvel,const float* __restrict__ bvel,
                             const float* __restrict__ whid,const float* __restrict__ bhid){
    int t = threadIdx.x;
    for (int k = t; k < 64*64; k += 256){
        int c = k >> 6, d = k & 63;
        int qt = d >> 4, dl = d & 15;
        g_wpack[qt*1028 + c*16 + dl] = w1[k];
    }
    for (int k = t; k < 64*32; k += 256){
        int c = k >> 5, d = k & 31;
        int qt = d >> 3, dl = d & 7;
        g_wpack[4112 + qt*516 + c*8 + dl] = w2[k];
    }
    for (int k = t; k < 256; k += 256) g_wpack[6172 + k] = whid[k];
    if (t < 96) g_wpack[6428 + t] = wrgb[t];
    if (t < 64) g_wpack[6524 + t] = wvel[t];
    if (t < 64) g_wpack[6588 + t] = b1[t];
    if (t < 32) g_wpack[6652 + t] = b2[t];
    if (t < 3)  g_wpack[6684 + t] = brgb[t];
    if (t < 2)  g_wpack[6687 + t] = bvel[t];
    if (t < 8)  g_wpack[6692 + t] = bhid[t];
}

// ---------------- kernel A: mask + noise + unfired fast path + compaction ----------------
__global__ __launch_bounds__(256)
void mask_kernel(const float* __restrict__ S, float* __restrict__ O){
    const int i    = blockIdx.x * 256 + threadIdx.x;
    const int lane = threadIdx.x & 31;

    uint32_t K0 = g_keys[0], K1 = g_keys[1];
    uint32_t A0 = g_keys[2], A1 = g_keys[3];
    uint32_t B0 = g_keys[4], B1 = g_keys[5];
    uint32_t ui = (uint32_t)i;

    float um = bits_to_u01(rng_bits(K0, K1, ui));
    int fired = (um < 0.5f);

    const float LO   = -0.99999994f;
    const float SPAN =  1.99999994f;
    float uxr = bits_to_u01(rng_bits(A0, A1, ui));
    float uyr = bits_to_u01(rng_bits(B0, B1, ui));
    float ux  = fmaxf(LO, uxr * SPAN + LO);
    float uy  = fmaxf(LO, uyr * SPAN + LO);
    float zx  = 1.41421356f * erfinv32(ux);
    float zy  = 1.41421356f * erfinv32(uy);

    const float4* S4 = (const float4*)S;
    size_t a = (size_t)i * 4;
    float4 v0 = __ldg(&S4[a+0]);
    float4 v1 = __ldg(&S4[a+1]);
    float4 v2 = __ldg(&S4[a+2]);
    float4 v3 = __ldg(&S4[a+3]);

    g_m0[i] = v0.w;

    if (fired){
        g_vxn[i] = zx;
        g_vyn[i] = zy;
    } else {
        float o0c = fminf(fmaxf(v0.x, 0.0f), 1.0f);
        float o1c = fminf(fmaxf(v0.y, 0.0f), 1.0f);
        float o2c = fminf(fmaxf(v0.z, 0.0f), 1.0f);
        float vx  = 0.95f * fminf(fmaxf(v1.x, -1.0f), 1.0f);
        float vy  = 0.95f * fminf(fmaxf(v1.y, -1.0f), 1.0f);

        float4* O4 = (float4*)O;
        size_t ob = (size_t)i * 4;
        O4[ob+0] = make_float4(o0c, o1c, o2c, v0.w);
        O4[ob+1] = make_float4(vx, vy, v1.z, v1.w);
        O4[ob+2] = v2;
        O4[ob+3] = v3;

        g_vxn[i] = vx + 0.2f * zx;
        g_vyn[i] = vy + 0.2f * zy;
    }

    unsigned bal = __ballot_sync(0xffffffffu, fired);
    int rank = __popc(bal & ((1u << lane) - 1u));
    int cnt  = __popc(bal);
    int base = 0;
    if (lane == 0 && cnt) base = atomicAdd(&g_count, cnt);
    base = __shfl_sync(0xffffffffu, base, 0);
    if (fired) g_list[base + rank] = i;
}

// ---------------- perception: compute + spill into swizzled smem column ----------------
__device__ __forceinline__ void perceive_spill(const float* __restrict__ S,
                                               int i, float* __restrict__ sb, int col){
    const int x = i & (W-1);
    const int y = (i >> 9) & (H-1);
    const int b = i >> 18;
    const int xm = (x-1)&(W-1), xp = (x+1)&(W-1);
    const int ym = (y-1)&(H-1), yp = (y+1)&(H-1);
    const size_t rowb = ((size_t)b) << 18;
    const float4* S4 = (const float4*)S;

#define PIXF4(yy,xx) ((rowb + (((size_t)(yy))<<9) + (size_t)(xx)) * 4)

    const ull one2  = pack2( 1.0f,  1.0f);
    const ull neg12 = pack2(-1.0f, -1.0f);
    const ull two2  = pack2( 2.0f,  2.0f);
    const ull neg22 = pack2(-2.0f, -2.0f);
    const ull neg42 = pack2(-4.0f, -4.0f);
    const ull eig2  = pack2(0.125f, 0.125f);
    const ull qtr2  = pack2(0.25f,  0.25f);

    ull pp[8], gx2[8], gy2[8], lap2[8];
    {
        size_t a = PIXF4(y,x);
#pragma unroll
        for (int q = 0; q < 4; q++){
            float4 v = __ldg(&S4[a+q]);
            pp[2*q+0] = pack2(v.x, v.y);
            pp[2*q+1] = pack2(v.z, v.w);
        }
#pragma unroll
        for (int k = 0; k < 8; k++){
            gx2[k] = 0ull; gy2[k] = 0ull;
            lap2[k] = fmul2(neg42, pp[k]);
        }
    }

#define NBRP(yy,xx,STMT) { size_t a = PIXF4(yy,xx); ull v2[8]; \
    _Pragma("unroll") for (int q = 0; q < 4; q++){ \
        float4 vv = __ldg(&S4[a+q]); \
        v2[2*q+0] = pack2(vv.x, vv.y); v2[2*q+1] = pack2(vv.z, vv.w); } \
    _Pragma("unroll") for (int k = 0; k < 8; k++){ ull v = v2[k]; STMT; } }

    NBRP(ym, xm, { gx2[k] = ffma2(neg12, v, gx2[k]); gy2[k] = ffma2(neg12, v, gy2[k]); })
    NBRP(ym, x , { gy2[k] = ffma2(neg22, v, gy2[k]); lap2[k] = ffma2(one2, v, lap2[k]); })
    NBRP(ym, xp, { gx2[k] = ffma2(one2 , v, gx2[k]); gy2[k] = ffma2(neg12, v, gy2[k]); })
    NBRP(y , xm, { gx2[k] = ffma2(neg22, v, gx2[k]); lap2[k] = ffma2(one2, v, lap2[k]); })
    NBRP(y , xp, { gx2[k] = ffma2(two2 , v, gx2[k]); lap2[k] = ffma2(one2, v, lap2[k]); })
    NBRP(yp, xm, { gx2[k] = ffma2(neg12, v, gx2[k]); gy2[k] = ffma2(one2 , v, gy2[k]); })
    NBRP(yp, x , { gy2[k] = ffma2(two2 , v, gy2[k]); lap2[k] = ffma2(one2, v, lap2[k]); })
    NBRP(yp, xp, { gx2[k] = ffma2(one2 , v, gx2[k]); gy2[k] = ffma2(one2 , v, gy2[k]); })
#undef NBRP
#undef PIXF4

#pragma unroll
    for (int k = 0; k < 8; k++){
        gx2[k]  = fmul2(eig2, gx2[k]);
        gy2[k]  = fmul2(eig2, gy2[k]);
        lap2[k] = fmul2(qtr2, lap2[k]);
    }

#pragma unroll
    for (int k = 0; k < 8; k++){
        float a0, a1;
        unpack2(pp[k],  a0, a1); sb[AOFF(2*k   , col)]=a0; sb[AOFF(2*k+ 1, col)]=a1;
        unpack2(gx2[k], a0, a1); sb[AOFF(16+2*k, col)]=a0; sb[AOFF(17+2*k, col)]=a1;
        unpack2(gy2[k], a0, a1); sb[AOFF(32+2*k, col)]=a0; sb[AOFF(33+2*k, col)]=a1;
        unpack2(lap2[k],a0, a1); sb[AOFF(48+2*k, col)]=a0; sb[AOFF(49+2*k, col)]=a1;
    }
}

// ---------------- epilogue: heads tail + state write for one pixel ----------------
__device__ __forceinline__ void finish_pixel(const float* __restrict__ S, float* __restrict__ O,
                                             int i, float r0, float r1, float r2,
                                             float dvx, float dvy, const ull* hid2){
    float hid[8];
#pragma unroll
    for (int jj = 0; jj < 4; jj++) unpack2(hid2[jj], hid[2*jj], hid[2*jj+1]);

    const float4* S4 = (const float4*)S;
    size_t a = (size_t)i * 4;
    float4 s0 = __ldg(&S4[a+0]);
    float4 s1 = __ldg(&S4[a+1]);
    float4 s2 = __ldg(&S4[a+2]);
    float4 s3 = __ldg(&S4[a+3]);

    float o0c = fminf(fmaxf(s0.x + r0, 0.0f), 1.0f);
    float o1c = fminf(fmaxf(s0.y + r1, 0.0f), 1.0f);
    float o2c = fminf(fmaxf(s0.z + r2, 0.0f), 1.0f);
    float vx  = 0.95f * fminf(fmaxf(s1.x + dvx, -1.0f), 1.0f);
    float vy  = 0.95f * fminf(fmaxf(s1.y + dvy, -1.0f), 1.0f);

    float4* O4 = (float4*)O;
    size_t ob = (size_t)i * 4;
    O4[ob+0] = make_float4(o0c, o1c, o2c, s0.w);  // ch3 overwritten by diffuse pass
    O4[ob+1] = make_float4(vx, vy, s1.z, s1.w);
    O4[ob+2] = make_float4(s2.x + hid[0], s2.y + hid[1], s2.z + hid[2], s2.w + hid[3]);
    O4[ob+3] = make_float4(s3.x + hid[4], s3.y + hid[5], s3.z + hid[6], s3.w + hid[7]);

    float zx = g_vxn[i];
    float zy = g_vyn[i];
    g_vxn[i] = vx + 0.2f * zx;
    g_vyn[i] = vy + 0.2f * zy;
}

// ---------------- kernel B: quarter-split lane quads, 8 px per quad ----------------
__global__ __launch_bounds__(128, 2)
void nca_fired_kernel(const float* __restrict__ S, float* __restrict__ O){
    extern __shared__ float smem_f[];
    const int tid = threadIdx.x;
    const int count = g_count;
    if (blockIdx.x * 256 >= count) return;     // uniform block exit

    // bulk copy packed weights (28KB) into smem
    {
        const float4* src = (const float4*)g_wpack;
        float4* dst = (float4*)(smem_f + ACT_F);
#pragma unroll
        for (int k = 0; k < 14; k++) dst[tid + 128*k] = src[tid + 128*k];
    }
    __syncthreads();

    const int q    = tid & 3;            // output quarter
    const int quad = tid >> 2;           // 0..31
    const int colb = quad * 8;           // act column base for quad's 8 px
    const int cm   = count - 1;
    const int jb   = blockIdx.x * 256 + quad * 8;

    // this lane's 2 target pixels: px indices 2q, 2q+1 within the quad
    int ja = jb + 2*q, jbn = ja + 1;
    bool va = (ja < count), vb = (jbn < count);
    int ia = g_list[ja <= cm ? ja : cm];
    int ib = g_list[jbn <= cm ? jbn : cm];

    float* sb = smem_f;
    const float* Wt = smem_f + ACT_F;

    perceive_spill(S, ia, sb, colb + 2*q);
    perceive_spill(S, ib, sb, colb + 2*q + 1);
    __syncwarp();

    // ---- layer 1: acc[p][d] = outputs (q*16+2d, +1) for quad pixel p ----
    ull acc[8][8];
    {
        const ull* b1u = (const ull*)(Wt + 6588);
#pragma unroll
        for (int d = 0; d < 8; d++){
            ull bv = b1u[q*8 + d];
#pragma unroll
            for (int p = 0; p < 8; p++) acc[p][d] = bv;
        }
    }
    {
        const ulonglong2* w1q = (const ulonglong2*)(Wt + q*1028);
#pragma unroll 2
        for (int c = 0; c < 64; c++){
            float4 a0 = *(const float4*)&sb[ACHUNK(c, 2*quad)];
            float4 a1 = *(const float4*)&sb[ACHUNK(c, 2*quad+1)];
            ull pk[8];
            pk[0]=pack2(a0.x,a0.x); pk[1]=pack2(a0.y,a0.y);
            pk[2]=pack2(a0.z,a0.z); pk[3]=pack2(a0.w,a0.w);
            pk[4]=pack2(a1.x,a1.x); pk[5]=pack2(a1.y,a1.y);
            pk[6]=pack2(a1.z,a1.z); pk[7]=pack2(a1.w,a1.w);
            const ulonglong2* wr = w1q + c*4;
#pragma unroll
            for (int j = 0; j < 4; j++){
                ulonglong2 wv = wr[j];
#pragma unroll
                for (int p = 0; p < 8; p++){
                    acc[p][2*j+0] = ffma2(pk[p], wv.x, acc[p][2*j+0]);
                    acc[p][2*j+1] = ffma2(pk[p], wv.y, acc[p][2*j+1]);
                }
            }
        }
    }
    // relu + store h rows (lane's 16 rows, quad's 8 columns)
#pragma unroll
    for (int d = 0; d < 8; d++){
        float lo[8], hi[8];
#pragma unroll
        for (int p = 0; p < 8; p++){ unpack2(acc[p][d], lo[p], hi[p]); }
        int r0 = q*16 + 2*d, r1 = r0 + 1;
        *(float4*)&sb[ACHUNK(r0, 2*quad  )] = make_float4(fmaxf(lo[0],0.f), fmaxf(lo[1],0.f), fmaxf(lo[2],0.f), fmaxf(lo[3],0.f));
        *(float4*)&sb[ACHUNK(r0, 2*quad+1)] = make_float4(fmaxf(lo[4],0.f), fmaxf(lo[5],0.f), fmaxf(lo[6],0.f), fmaxf(lo[7],0.f));
        *(float4*)&sb[ACHUNK(r1, 2*quad  )] = make_float4(fmaxf(hi[0],0.f), fmaxf(hi[1],0.f), fmaxf(hi[2],0.f), fmaxf(hi[3],0.f));
        *(float4*)&sb[ACHUNK(r1, 2*quad+1)] = make_float4(fmaxf(hi[4],0.f), fmaxf(hi[5],0.f), fmaxf(hi[6],0.f), fmaxf(hi[7],0.f));
    }
    __syncwarp();

    // ---- layer 2: xacc[p][t] = outputs (q*8+2t, +1) for quad pixel p ----
    ull xacc[8][4];
    {
        const ull* b2u = (const ull*)(Wt + 6652);
#pragma unroll
        for (int t = 0; t < 4; t++){
            ull bv = b2u[q*4 + t];
#pragma unroll
            for (int p = 0; p < 8; p++) xacc[p][t] = bv;
        }
    }
    {
        const ulonglong2* w2q = (const ulonglong2*)(Wt + 4112 + q*516);
#pragma unroll 2
        for (int c = 0; c < 64; c++){
            float4 a0 = *(const float4*)&sb[ACHUNK(c, 2*quad)];
            float4 a1 = *(const float4*)&sb[ACHUNK(c, 2*quad+1)];
            ull pk[8];
            pk[0]=pack2(a0.x,a0.x); pk[1]=pack2(a0.y,a0.y);
            pk[2]=pack2(a0.z,a0.z); pk[3]=pack2(a0.w,a0.w);
            pk[4]=pack2(a1.x,a1.x); pk[5]=pack2(a1.y,a1.y);
            pk[6]=pack2(a1.z,a1.z); pk[7]=pack2(a1.w,a1.w);
            const ulonglong2* wr = w2q + c*2;
            ulonglong2 wv0 = wr[0], wv1 = wr[1];
#pragma unroll
            for (int p = 0; p < 8; p++){
                xacc[p][0] = ffma2(pk[p], wv0.x, xacc[p][0]);
                xacc[p][1] = ffma2(pk[p], wv0.y, xacc[p][1]);
                xacc[p][2] = ffma2(pk[p], wv1.x, xacc[p][2]);
                xacc[p][3] = ffma2(pk[p], wv1.y, xacc[p][3]);
            }
        }
    }
    __syncwarp();   // all reads of h done before overwriting rows 0..31 with xo
    // store xo (pre-relu) into act rows 0..31
#pragma unroll
    for (int t = 0; t < 4; t++){
        float lo[8], hi[8];
#pragma unroll
        for (int p = 0; p < 8; p++){ unpack2(xacc[p][t], lo[p], hi[p]); }
        int r0 = q*8 + 2*t, r1 = r0 + 1;
        *(float4*)&sb[ACHUNK(r0, 2*quad  )] = make_float4(lo[0], lo[1], lo[2], lo[3]);
        *(float4*)&sb[ACHUNK(r0, 2*quad+1)] = make_float4(lo[4], lo[5], lo[6], lo[7]);
        *(float4*)&sb[ACHUNK(r1, 2*quad  )] = make_float4(hi[0], hi[1], hi[2], hi[3]);
        *(float4*)&sb[ACHUNK(r1, 2*quad+1)] = make_float4(hi[4], hi[5], hi[6], hi[7]);
    }
    __syncwarp();

    // ---- heads for the lane's 2 pixels (read both from one float2/row) ----
    const ull*  whu   = (const ull*)(Wt + 6172);
    const float* wrgb = Wt + 6428;
    const float* wvel = Wt + 6524;
    const float* brgb = Wt + 6684;
    const float* bvel = Wt + 6687;
    const ull*  bhu   = (const ull*)(Wt + 6692);

    float r0a = brgb[0], r1a = brgb[1], r2a = brgb[2];
    float r0b = r0a, r1b = r1a, r2b = r2a;
    float dvxa = bvel[0], dvya = bvel[1];
    float dvxb = dvxa, dvyb = dvya;
    ull hid2a[4], hid2b[4];
    {
        const ulonglong2* bp = (const ulonglong2*)bhu;
        ulonglong2 bv0 = bp[0], bv1 = bp[1];
        hid2a[0] = bv0.x; hid2a[1] = bv0.y; hid2a[2] = bv1.x; hid2a[3] = bv1.y;
        hid2b[0] = bv0.x; hid2b[1] = bv0.y; hid2b[2] = bv1.x; hid2b[3] = bv1.y;
    }
    const int xk = 2*quad + (q >> 1);        // chunk holding cols colb+2q, +2q+1
    const int xoff = 2*(q & 1);              // float offset within chunk
#pragma unroll
    for (int c = 0; c < 32; c++){
        float2 xv = *(const float2*)&sb[ACHUNK(c, xk) + xoff];
        float xa = fmaxf(xv.x, 0.0f);
        float xb = fmaxf(xv.y, 0.0f);
        r0a  = fmaf(xa, wrgb[c*3+0], r0a);
        r1a  = fmaf(xa, wrgb[c*3+1], r1a);
        r2a  = fmaf(xa, wrgb[c*3+2], r2a);
        dvxa = fmaf(xa, wvel[c*2+0], dvxa);
        dvya = fmaf(xa, wvel[c*2+1], dvya);
        r0b  = fmaf(xb, wrgb[c*3+0], r0b);
        r1b  = fmaf(xb, wrgb[c*3+1], r1b);
        r2b  = fmaf(xb, wrgb[c*3+2], r2b);
        dvxb = fmaf(xb, wvel[c*2+0], dvxb);
        dvyb = fmaf(xb, wvel[c*2+1], dvyb);
        const ulonglong2* wh = (const ulonglong2*)(whu + c*4);
        ulonglong2 w0 = wh[0], w1v = wh[1];
        ull xa2 = pack2(xa, xa);
        ull xb2 = pack2(xb, xb);
        hid2a[0] = ffma2(xa2, w0.x,  hid2a[0]);
        hid2a[1] = ffma2(xa2, w0.y,  hid2a[1]);
        hid2a[2] = ffma2(xa2, w1v.x, hid2a[2]);
        hid2a[3] = ffma2(xa2, w1v.y, hid2a[3]);
        hid2b[0] = ffma2(xb2, w0.x,  hid2b[0]);
        hid2b[1] = ffma2(xb2, w0.y,  hid2b[1]);
        hid2b[2] = ffma2(xb2, w1v.x, hid2b[2]);
        hid2b[3] = ffma2(xb2, w1v.y, hid2b[3]);
    }

    if (va) finish_pixel(S, O, ia, r0a, r1a, r2a, dvxa, dvya, hid2a);
    if (vb) finish_pixel(S, O, ib, r0b, r1b, r2b, dvxb, dvyb, hid2b);
}

// ---------------- advection (semi-Lagrangian, periodic bilinear) ----------------
__global__ void advect_kernel(const float* __restrict__ src, float* __restrict__ dst){
    int i = blockIdx.x * blockDim.x + threadIdx.x;
    int x = i & (W-1);
    int y = (i >> 9) & (H-1);
    int b = i >> 18;
    float vx = g_vxn[i], vy = g_vyn[i];
    float sy = (float)y - vy * 0.25f;
    float sx = (float)x - vx * 0.25f;
    float y0f = floorf(sy), x0f = floorf(sx);
    float fy = sy - y0f, fx = sx - x0f;
    int y0 = ((int)y0f) & (H-1);
    int x0 = ((int)x0f) & (W-1);
    int y1 = (y0 + 1) & (H-1);
    int x1 = (x0 + 1) & (W-1);
    int base = b << 18;
    float m00 = __ldg(&src[base + (y0<<9) + x0]);
    float m01 = __ldg(&src[base + (y0<<9) + x1]);
    float m10 = __ldg(&src[base + (y1<<9) + x0]);
    float m11 = __ldg(&src[base + (y1<<9) + x1]);
    dst[i] = (1.0f - fy) * ((1.0f - fx) * m00 + fx * m01)
           +         fy  * ((1.0f - fx) * m10 + fx * m11);
}

// ---------------- diffuse + write mass channel ----------------
__global__ void diffuse_kernel(const float* __restrict__ mb, float* __restrict__ O){
    int i = blockIdx.x * blockDim.x + threadIdx.x;
    int x = i & (W-1);
    int y = (i >> 9) & (H-1);
    int b = i >> 18;
    int xm = (x-1)&(W-1), xp = (x+1)&(W-1);
    int ym = (y-1)&(H-1), yp = (y+1)&(H-1);
    int base = b << 18;
    float mc  = mb[i];
    float avg = (__ldg(&mb[base + (y<<9)  + xp])
               + __ldg(&mb[base + (y<<9)  + xm])
               + __ldg(&mb[base + (yp<<9) + x ])
               + __ldg(&mb[base + (ym<<9) + x ])) / 4.0f;
    O[(size_t)i * 16 + 3] = mc + 0.05f * (avg - mc);
}

// ---------------- launch ----------------
extern "C" void kernel_launch(void* const* d_in, const int* in_sizes, int n_in,
                              void* d_out, int out_size){
    const float* state = (const float*)d_in[0];
    const int*   seed  = (const int*)d_in[1];

    cudaFuncSetAttribute(nca_fired_kernel,
                         cudaFuncAttributeMaxDynamicSharedMemorySize, SMEM_TOTAL_B);

    key_setup<<<1, 1>>>(seed);
    prep_weights<<<1, 256>>>((const float*)d_in[2], (const float*)d_in[3],
                             (const float*)d_in[4], (const float*)d_in[5],
                             (const float*)d_in[6], (const float*)d_in[7],
                             (const float*)d_in[8], (const float*)d_in[9],
                             (const float*)d_in[10], (const float*)d_in[11]);

    float *m0, *m1;
    cudaGetSymbolAddress((void**)&m0, g_m0);
    cudaGetSymbolAddress((void**)&m1, g_m1);

    mask_kernel<<<NPIX/256, 256>>>(state, (float*)d_out);
    nca_fired_kernel<<<NPIX/256, 128, SMEM_TOTAL_B>>>(state, (float*)d_out);
    advect_kernel<<<NPIX/256, 256>>>(m0, m1);
    advect_kernel<<<NPIX/256, 256>>>(m1, m0);
    diffuse_kernel<<<NPIX/256, 256>>>(m0, (float*)d_out);
}